// round 1
// baseline (speedup 1.0000x reference)
#include <cuda_runtime.h>
#include <cfloat>

// Problem geometry (fixed by the reference): planes of 128x128, B*C planes.
constexpr int W_DIM   = 128;
constexpr int HW      = 128 * 128;     // 16384 elements per (b,c) plane
constexpr int THREADS = 512;
constexpr int V4      = HW / 4;        // 4096 float4 per plane
constexpr int PER     = V4 / THREADS;  // 8 float4 per thread

__device__ __forceinline__ float warp_sum(float v) {
    #pragma unroll
    for (int o = 16; o > 0; o >>= 1) v += __shfl_down_sync(0xffffffffu, v, o);
    return v;
}
__device__ __forceinline__ float warp_min(float v) {
    #pragma unroll
    for (int o = 16; o > 0; o >>= 1) v = fminf(v, __shfl_down_sync(0xffffffffu, v, o));
    return v;
}
__device__ __forceinline__ float warp_max(float v) {
    #pragma unroll
    for (int o = 16; o > 0; o >>= 1) v = fmaxf(v, __shfl_down_sync(0xffffffffu, v, o));
    return v;
}

__global__ __launch_bounds__(THREADS)
void hm2kp_kernel(const float* __restrict__ in,
                  float* __restrict__ map_out,
                  float* __restrict__ kp_out,
                  float* __restrict__ zeta_out)
{
    __shared__ float s_r0[16], s_r1[16], s_r2[16];
    __shared__ float s_bmin, s_bmax;

    const int bc   = blockIdx.x;
    const int tid  = threadIdx.x;
    const int lane = tid & 31;
    const int wid  = tid >> 5;

    const float4* __restrict__ inp  = reinterpret_cast<const float4*>(in) + (size_t)bc * V4;
    float4* __restrict__       outp = reinterpret_cast<float4*>(map_out) + (size_t)bc * V4;

    // ---- Phase 1: load whole plane into registers, compute local min/max ----
    float4 v[PER];
    float lmin = FLT_MAX, lmax = -FLT_MAX;
    #pragma unroll
    for (int i = 0; i < PER; ++i) {
        v[i] = inp[tid + i * THREADS];
        lmin = fminf(lmin, fminf(fminf(v[i].x, v[i].y), fminf(v[i].z, v[i].w)));
        lmax = fmaxf(lmax, fmaxf(fmaxf(v[i].x, v[i].y), fmaxf(v[i].z, v[i].w)));
    }

    // ---- Block reduce min/max (16 warps) ----
    lmin = warp_min(lmin);
    lmax = warp_max(lmax);
    if (lane == 0) { s_r0[wid] = lmin; s_r1[wid] = lmax; }
    __syncthreads();
    if (wid == 0) {
        float m0 = (lane < 16) ? s_r0[lane] :  FLT_MAX;
        float m1 = (lane < 16) ? s_r1[lane] : -FLT_MAX;
        m0 = warp_min(m0);
        m1 = warp_max(m1);
        if (lane == 0) { s_bmin = m0; s_bmax = m1; }
    }
    __syncthreads();

    const float bmin = s_bmin;
    const float rcp  = 1.0f / s_bmax;   // reference divides by max (not max-min)

    // ---- Phase 2: normalize, accumulate zeta / x-weighted / y-weighted sums ----
    float sum = 0.f, sx = 0.f, sy = 0.f;
    #pragma unroll
    for (int i = 0; i < PER; ++i) {
        const int i4   = tid + i * THREADS;
        const int base = i4 << 2;                  // element index in plane
        const float w0 = (float)(base & (W_DIM - 1));
        const float hh = (float)(base >> 7);       // row index (4 | 128, so constant per vec)

        const float m0 = (v[i].x - bmin) * rcp;
        const float m1 = (v[i].y - bmin) * rcp;
        const float m2 = (v[i].z - bmin) * rcp;
        const float m3 = (v[i].w - bmin) * rcp;

        const float s4 = (m0 + m1) + (m2 + m3);
        sum += s4;
        sx  += m0 * w0 + m1 * (w0 + 1.f) + m2 * (w0 + 2.f) + m3 * (w0 + 3.f);
        sy  += s4 * hh;

        outp[i4] = make_float4(m0, m1, m2, m3);
    }

    // ---- Block reduce the three sums ----
    sum = warp_sum(sum);
    sx  = warp_sum(sx);
    sy  = warp_sum(sy);
    if (lane == 0) { s_r0[wid] = sum; s_r1[wid] = sx; s_r2[wid] = sy; }
    __syncthreads();
    if (wid == 0) {
        float a = (lane < 16) ? s_r0[lane] : 0.f;
        float b = (lane < 16) ? s_r1[lane] : 0.f;
        float c = (lane < 16) ? s_r2[lane] : 0.f;
        a = warp_sum(a);
        b = warp_sum(b);
        c = warp_sum(c);
        if (lane == 0) {
            kp_out[(size_t)bc * 2 + 0] = rintf(b / a);  // round(get_kp_x / zeta)
            kp_out[(size_t)bc * 2 + 1] = rintf(c / a);  // round(get_kp_y / zeta)
            zeta_out[bc] = a;
        }
    }
}

extern "C" void kernel_launch(void* const* d_in, const int* in_sizes, int n_in,
                              void* d_out, int out_size)
{
    const float* in = (const float*)d_in[0];
    const int total  = in_sizes[0];        // B*C*H*W
    const int planes = total / HW;         // B*C = 6400

    float* map  = (float*)d_out;                       // [B,C,H,W]
    float* kp   = map + (size_t)total;                 // [B,C,2]
    float* zeta = kp + (size_t)planes * 2;             // [B,C]

    hm2kp_kernel<<<planes, THREADS>>>(in, map, kp, zeta);
}

// round 2
// speedup vs baseline: 1.0028x; 1.0028x over previous
#include <cuda_runtime.h>
#include <cfloat>

// Problem geometry (fixed by the reference): planes of 128x128, B*C planes.
constexpr int W_DIM   = 128;
constexpr int HW      = 128 * 128;     // 16384 elements per (b,c) plane
constexpr int THREADS = 1024;
constexpr int V4      = HW / 4;        // 4096 float4 per plane
constexpr int PER     = V4 / THREADS;  // 4 float4 per thread
// Sum of x coordinates over the whole plane: H * sum_{x=0..127} x = 128 * 8128
constexpr float SUM_XW = 1040384.0f;   // same for y by symmetry

__device__ __forceinline__ float warp_sum(float v) {
    #pragma unroll
    for (int o = 16; o > 0; o >>= 1) v += __shfl_down_sync(0xffffffffu, v, o);
    return v;
}
__device__ __forceinline__ float warp_min(float v) {
    #pragma unroll
    for (int o = 16; o > 0; o >>= 1) v = fminf(v, __shfl_down_sync(0xffffffffu, v, o));
    return v;
}
__device__ __forceinline__ float warp_max(float v) {
    #pragma unroll
    for (int o = 16; o > 0; o >>= 1) v = fmaxf(v, __shfl_down_sync(0xffffffffu, v, o));
    return v;
}

__global__ __launch_bounds__(THREADS, 2)
void hm2kp_kernel(const float* __restrict__ in,
                  float* __restrict__ map_out,
                  float* __restrict__ kp_out,
                  float* __restrict__ zeta_out)
{
    __shared__ float s_r0[32], s_r1[32], s_r2[32], s_r3[32], s_r4[32];
    __shared__ float s_bmin, s_rcp;

    const int bc   = blockIdx.x;
    const int tid  = threadIdx.x;
    const int lane = tid & 31;
    const int wid  = tid >> 5;

    const float4* __restrict__ inp  = reinterpret_cast<const float4*>(in) + (size_t)bc * V4;
    float4* __restrict__       outp = reinterpret_cast<float4*>(map_out) + (size_t)bc * V4;

    // ---- Phase 1: load plane into registers; accumulate min/max and RAW
    //      weighted sums (reductions on raw values; /max and -min applied
    //      analytically afterwards, so phase 2 is a pure stream). ----
    float4 v[PER];
    float lmin = FLT_MAX, lmax = -FLT_MAX;
    float sr = 0.f, sxr = 0.f, syr = 0.f;
    #pragma unroll
    for (int i = 0; i < PER; ++i) {
        v[i] = __ldcs(&inp[tid + i * THREADS]);
        lmin = fminf(lmin, fminf(fminf(v[i].x, v[i].y), fminf(v[i].z, v[i].w)));
        lmax = fmaxf(lmax, fmaxf(fmaxf(v[i].x, v[i].y), fmaxf(v[i].z, v[i].w)));

        const int base = (tid + i * THREADS) << 2;       // element index in plane
        const float x0 = (float)(base & (W_DIM - 1));
        const float yy = (float)(base >> 7);             // row (constant per float4)

        const float s4 = (v[i].x + v[i].y) + (v[i].z + v[i].w);
        sr  += s4;
        sxr += v[i].x * x0 + v[i].y * (x0 + 1.f) + v[i].z * (x0 + 2.f) + v[i].w * (x0 + 3.f);
        syr += s4 * yy;
    }

    // ---- Block reduce: min, max, sum, sum*x, sum*y (32 warps) ----
    lmin = warp_min(lmin);
    lmax = warp_max(lmax);
    sr   = warp_sum(sr);
    sxr  = warp_sum(sxr);
    syr  = warp_sum(syr);
    if (lane == 0) {
        s_r0[wid] = lmin; s_r1[wid] = lmax;
        s_r2[wid] = sr;   s_r3[wid] = sxr;  s_r4[wid] = syr;
    }
    __syncthreads();
    if (wid == 0) {
        float m0 = warp_min(s_r0[lane]);
        float m1 = warp_max(s_r1[lane]);
        float a  = warp_sum(s_r2[lane]);
        float b  = warp_sum(s_r3[lane]);
        float c  = warp_sum(s_r4[lane]);
        if (lane == 0) {
            const float rcp = 1.0f / m1;        // reference divides by max (not max-min)
            s_bmin = m0;
            s_rcp  = rcp;
            // zeta = sum((v - min)/max) = (S - HW*min)/max
            const float denom = a - (float)HW * m0;
            zeta_out[bc] = denom * rcp;
            // kp = round(((Sv*w - min*Sum_w)/max) / zeta) — the /max cancels
            kp_out[(size_t)bc * 2 + 0] = rintf((b - m0 * SUM_XW) / denom);
            kp_out[(size_t)bc * 2 + 1] = rintf((c - m0 * SUM_XW) / denom);
        }
    }
    __syncthreads();

    const float bmin = s_bmin;
    const float rcp  = s_rcp;

    // ---- Phase 2: pure normalize + stream out ----
    #pragma unroll
    for (int i = 0; i < PER; ++i) {
        float4 o;
        o.x = (v[i].x - bmin) * rcp;
        o.y = (v[i].y - bmin) * rcp;
        o.z = (v[i].z - bmin) * rcp;
        o.w = (v[i].w - bmin) * rcp;
        __stcs(&outp[tid + i * THREADS], o);
    }
}

extern "C" void kernel_launch(void* const* d_in, const int* in_sizes, int n_in,
                              void* d_out, int out_size)
{
    const float* in = (const float*)d_in[0];
    const int total  = in_sizes[0];        // B*C*H*W
    const int planes = total / HW;         // B*C = 6400

    float* map  = (float*)d_out;                       // [B,C,H,W]
    float* kp   = map + (size_t)total;                 // [B,C,2]
    float* zeta = kp + (size_t)planes * 2;             // [B,C]

    hm2kp_kernel<<<planes, THREADS>>>(in, map, kp, zeta);
}